// round 9
// baseline (speedup 1.0000x reference)
#include <cuda_runtime.h>

// FactorizedSpectralConv2d: x[32,64,128,128] f32, w0/w1[64,64,32,2] f32.
// out[b,o,m,n] = irfft_n( trunc32(rfft_n(x)) @ w0 ) + irfft_m( trunc32(rfft_m(x)) @ w1 )
// Implemented as 3 dense GEMM stages per branch with f-planar intermediate
// layouts so every global access is contiguous.

#define SQI 0.08838834764831843f   // 1/sqrt(128)

// ---- device-global scratch (allocation-free rule) ----
__device__ float g_Ffwd[128 * 64];        // [k][2f|2f+1]  fwd DFT basis (incl 1/sqrt(128))
__device__ float g_Finv[64 * 128];        // [s][n]        inv basis (incl 1/sqrt(128), x2 for f>=1, 0 for Im DC)
__device__ float g_w0re[32 * 64 * 64];    // [f][i][o]
__device__ float g_w0im[32 * 64 * 64];
__device__ float g_w1re[32 * 64 * 64];
__device__ float g_w1im[32 * 64 * 64];
__device__ float g_Xf[64 * 32 * 64 * 128]; // [s][b][i][m|n]  67 MB
__device__ float g_Yp[64 * 32 * 64 * 128]; // [s][b][o][m|n]  67 MB

// ---------------------------------------------------------------------------
// K0: build DFT bases + transpose weights to [f][i][o] planes.
// idx ranges: [0,8192) Ffwd, [8192,16384) Finv, [16384, 16384+4*131072) weights
__global__ __launch_bounds__(256) void k_init(const float* __restrict__ w0,
                                              const float* __restrict__ w1) {
    int idx = blockIdx.x * 256 + threadIdx.x;
    if (idx < 8192) {
        int k = idx >> 6, s = idx & 63;
        int f = s >> 1, c = s & 1;
        int t = (f * k) & 127;
        float sp, cp;
        sincospif((float)t * (1.0f / 64.0f), &sp, &cp);   // angle = 2*pi*t/128
        g_Ffwd[idx] = c ? (-SQI * sp) : (SQI * cp);
    } else if (idx < 16384) {
        int j = idx - 8192;
        int s = j >> 7, n = j & 127;
        int f = s >> 1, c = s & 1;
        int t = (f * n) & 127;
        float sp, cp;
        sincospif((float)t * (1.0f / 64.0f), &sp, &cp);
        float cf = (f == 0) ? SQI : (2.0f * SQI);          // DC unpaired; others x2
        g_Finv[j] = c ? (-cf * sp) : (cf * cp);            // f=0,c=1 -> sin(0)=0: Im(DC) ignored
    } else if (idx < 16384 + 4 * 131072) {
        int q = idx - 16384;
        int sel = q >> 17;           // 0:w0re 1:w0im 2:w1re 3:w1im
        int r = q & 131071;          // r = f*4096 + i*64 + o
        int f = r >> 12, i = (r >> 6) & 63, o = r & 63;
        const float* w = (sel >= 2) ? w1 : w0;
        float v = w[((i * 64 + o) * 32 + f) * 2 + (sel & 1)];
        if (sel == 0) g_w0re[r] = v;
        else if (sel == 1) g_w0im[r] = v;
        else if (sel == 2) g_w1re[r] = v;
        else g_w1im[r] = v;
    }
}

// ---------------------------------------------------------------------------
// K1a: forward DFT along last axis. Block = one (b,i): [128m x 128k] @ [128k x 64s].
// Output staged through smem -> planar g_Xf[s][b][i][m] with contiguous 512B rows.
__global__ __launch_bounds__(256) void k_fwd_y(const float* __restrict__ x) {
    extern __shared__ float sm[];
    float* As = sm;            // [128][36]  x tile (row-major m,k)
    float* Bs = sm + 4608;     // [32][64]   Ffwd chunk
    float* Ts = sm;            // [64][132]  output staging (reuses As/Bs after sync)

    int tid = threadIdx.x;
    int tx = tid & 15, ty = tid >> 4;
    int bi = blockIdx.x;
    const float* xr = x + (size_t)bi * 16384;

    float acc[8][4] = {};
    for (int kc = 0; kc < 4; ++kc) {
#pragma unroll
        for (int l = 0; l < 4; ++l) {                      // 128x32 floats
            int v = tid + l * 256;
            int row = v >> 3, kk = (v & 7) << 2;
            *(float4*)(As + row * 36 + kk) =
                *(const float4*)(xr + row * 128 + kc * 32 + kk);
        }
#pragma unroll
        for (int l = 0; l < 2; ++l) {                      // 32x64 floats
            int v = tid + l * 256;
            int kr = v >> 4, s4 = (v & 15) << 2;
            *(float4*)(Bs + kr * 64 + s4) =
                *(const float4*)(g_Ffwd + (kc * 32 + kr) * 64 + s4);
        }
        __syncthreads();
#pragma unroll 8
        for (int k = 0; k < 32; ++k) {
            float a[8];
#pragma unroll
            for (int j = 0; j < 8; ++j) a[j] = As[(ty * 8 + j) * 36 + k];
            float4 b4 = *(float4*)(Bs + k * 64 + tx * 4);
            float bb[4] = {b4.x, b4.y, b4.z, b4.w};
#pragma unroll
            for (int j = 0; j < 8; ++j)
#pragma unroll
                for (int c = 0; c < 4; ++c) acc[j][c] += a[j] * bb[c];
        }
        __syncthreads();
    }
#pragma unroll
    for (int j = 0; j < 8; ++j)
#pragma unroll
        for (int c = 0; c < 4; ++c)
            Ts[(tx * 4 + c) * 132 + ty * 8 + j] = acc[j][c];
    __syncthreads();
#pragma unroll
    for (int l = 0; l < 8; ++l) {                          // 64 rows of 128 floats
        int v = tid + l * 256;
        int s = v >> 5, m4 = (v & 31) << 2;
        *(float4*)(g_Xf + (s * 2048 + bi) * 128 + m4) = *(float4*)(Ts + s * 132 + m4);
    }
}

// K1b: forward DFT along axis -2 (contract over m). Block = one (b,i):
// T[n][s] = sum_m x[m][n] * Ffwd[m][s].
__global__ __launch_bounds__(256) void k_fwd_x(const float* __restrict__ x) {
    extern __shared__ float sm[];
    float* As = sm;            // [32][132]  x chunk (k=m rows, n cols)
    float* Bs = sm + 4224;     // [32][64]
    float* Ts = sm;            // [64][132]

    int tid = threadIdx.x;
    int tx = tid & 15, ty = tid >> 4;
    int bi = blockIdx.x;
    const float* xr = x + (size_t)bi * 16384;

    float acc[8][4] = {};
    for (int kc = 0; kc < 4; ++kc) {
#pragma unroll
        for (int l = 0; l < 4; ++l) {                      // 32x128 floats
            int v = tid + l * 256;
            int kr = v >> 5, n4 = (v & 31) << 2;
            *(float4*)(As + kr * 132 + n4) =
                *(const float4*)(xr + (kc * 32 + kr) * 128 + n4);
        }
#pragma unroll
        for (int l = 0; l < 2; ++l) {
            int v = tid + l * 256;
            int kr = v >> 4, s4 = (v & 15) << 2;
            *(float4*)(Bs + kr * 64 + s4) =
                *(const float4*)(g_Ffwd + (kc * 32 + kr) * 64 + s4);
        }
        __syncthreads();
#pragma unroll 8
        for (int k = 0; k < 32; ++k) {
            float a[8];
#pragma unroll
            for (int j = 0; j < 8; ++j) a[j] = As[k * 132 + ty * 8 + j];
            float4 b4 = *(float4*)(Bs + k * 64 + tx * 4);
            float bb[4] = {b4.x, b4.y, b4.z, b4.w};
#pragma unroll
            for (int j = 0; j < 8; ++j)
#pragma unroll
                for (int c = 0; c < 4; ++c) acc[j][c] += a[j] * bb[c];
        }
        __syncthreads();
    }
#pragma unroll
    for (int j = 0; j < 8; ++j)
#pragma unroll
        for (int c = 0; c < 4; ++c)
            Ts[(tx * 4 + c) * 132 + ty * 8 + j] = acc[j][c];
    __syncthreads();
#pragma unroll
    for (int l = 0; l < 8; ++l) {
        int v = tid + l * 256;
        int s = v >> 5, n4 = (v & 31) << 2;
        *(float4*)(g_Xf + (s * 2048 + bi) * 128 + n4) = *(float4*)(Ts + s * 132 + n4);
    }
}

// ---------------------------------------------------------------------------
// K2: per-mode complex channel mix. Block = (f, b, m-half):
//   Y[o][m] = sum_i conj-free complex mult: (Xr + iXi)(wre + i wim)
// Weights are L2-resident planar [f][i][o].
__global__ __launch_bounds__(256) void k_mix(int branch) {
    extern __shared__ float sm[];
    float* Wr = sm;                 // [64][68]
    float* Wi = sm + 64 * 68;
    float* Xr = sm + 2 * 64 * 68;   // [64 i][64 m]
    float* Xi = sm + 3 * 64 * 68;

    int tid = threadIdx.x;
    int bx = blockIdx.x;
    int f = bx >> 6;
    int b = (bx >> 1) & 31;
    int mh = bx & 1;

    const float* wpr = (branch ? g_w1re : g_w0re) + f * 4096;
    const float* wpi = (branch ? g_w1im : g_w0im) + f * 4096;
    int xbase = ((2 * f) * 2048 + b * 64) * 128 + mh * 64;   // + i*128

#pragma unroll
    for (int l = 0; l < 4; ++l) {
        int v = tid + l * 256;
        int i = v >> 4, c4 = (v & 15) << 2;
        *(float4*)(Wr + i * 68 + c4) = *(const float4*)(wpr + i * 64 + c4);
        *(float4*)(Wi + i * 68 + c4) = *(const float4*)(wpi + i * 64 + c4);
        *(float4*)(Xr + i * 68 + c4) = *(const float4*)(g_Xf + xbase + i * 128 + c4);
        *(float4*)(Xi + i * 68 + c4) = *(const float4*)(g_Xf + xbase + 262144 + i * 128 + c4);
    }
    __syncthreads();

    int ot = tid & 7, mt = tid >> 3;
    int m2 = mt * 2;
    float yr0[8] = {}, yr1[8] = {}, yi0[8] = {}, yi1[8] = {};
#pragma unroll 4
    for (int i = 0; i < 64; ++i) {
        float xr0 = Xr[i * 68 + m2], xr1 = Xr[i * 68 + m2 + 1];
        float xm0 = Xi[i * 68 + m2], xm1 = Xi[i * 68 + m2 + 1];
        float4 wa = *(float4*)(Wr + i * 68 + ot * 8);
        float4 wb = *(float4*)(Wr + i * 68 + ot * 8 + 4);
        float4 va = *(float4*)(Wi + i * 68 + ot * 8);
        float4 vb = *(float4*)(Wi + i * 68 + ot * 8 + 4);
        float wr8[8] = {wa.x, wa.y, wa.z, wa.w, wb.x, wb.y, wb.z, wb.w};
        float wi8[8] = {va.x, va.y, va.z, va.w, vb.x, vb.y, vb.z, vb.w};
#pragma unroll
        for (int oo = 0; oo < 8; ++oo) {
            yr0[oo] += wr8[oo] * xr0 - wi8[oo] * xm0;
            yr1[oo] += wr8[oo] * xr1 - wi8[oo] * xm1;
            yi0[oo] += wr8[oo] * xm0 + wi8[oo] * xr0;
            yi1[oo] += wr8[oo] * xm1 + wi8[oo] * xr1;
        }
    }
    int mg = mh * 64 + m2;
    int ybase = ((2 * f) * 32 + b) * 64;
#pragma unroll
    for (int oo = 0; oo < 8; ++oo) {
        int o = ot * 8 + oo;
        float* pr = g_Yp + (ybase + o) * 128 + mg;
        *(float2*)pr = make_float2(yr0[oo], yr1[oo]);
        *(float2*)(pr + 262144) = make_float2(yi0[oo], yi1[oo]);  // Im plane (s+1)
    }
}

// ---------------------------------------------------------------------------
// K3: inverse DFT. Block = one (b,o): out tile [128m x 128n], K = 64 spectral.
// branch 0 (width):  A = Y[s][m],    B = Finv[s][n]  -> write
// branch 1 (height): A = Finv[s][m], B = Y[s][n]     -> accumulate (+=)
// (operand-role swap makes m the row index in both -> coalesced epilogue)
__global__ __launch_bounds__(256) void k_inv(float* __restrict__ out, int branch) {
    extern __shared__ float sm[];
    float* As = sm;            // [64][132]
    float* Bs = sm + 64 * 132;

    int tid = threadIdx.x;
    int bo = blockIdx.x;
#pragma unroll
    for (int l = 0; l < 8; ++l) {
        int v = tid + l * 256;
        int s = v >> 5, c4 = (v & 31) << 2;
        float4 ya = *(const float4*)(g_Yp + (s * 2048 + bo) * 128 + c4);
        float4 fa = *(const float4*)(g_Finv + s * 128 + c4);
        if (branch == 0) {
            *(float4*)(As + s * 132 + c4) = ya;
            *(float4*)(Bs + s * 132 + c4) = fa;
        } else {
            *(float4*)(As + s * 132 + c4) = fa;
            *(float4*)(Bs + s * 132 + c4) = ya;
        }
    }
    __syncthreads();

    int tx = tid & 15, ty = tid >> 4;
    int n0 = tx * 8, m0 = ty * 8;
    float acc[8][8] = {};
#pragma unroll 4
    for (int s = 0; s < 64; ++s) {
        float4 a0 = *(float4*)(As + s * 132 + m0);
        float4 a1 = *(float4*)(As + s * 132 + m0 + 4);
        float4 b0 = *(float4*)(Bs + s * 132 + n0);
        float4 b1 = *(float4*)(Bs + s * 132 + n0 + 4);
        float av[8] = {a0.x, a0.y, a0.z, a0.w, a1.x, a1.y, a1.z, a1.w};
        float bv[8] = {b0.x, b0.y, b0.z, b0.w, b1.x, b1.y, b1.z, b1.w};
#pragma unroll
        for (int j = 0; j < 8; ++j)
#pragma unroll
            for (int c = 0; c < 8; ++c) acc[j][c] += av[j] * bv[c];
    }

    float* op = out + (size_t)bo * 16384;
    if (branch == 0) {
#pragma unroll
        for (int j = 0; j < 8; ++j) {
            *(float4*)(op + (m0 + j) * 128 + n0) =
                make_float4(acc[j][0], acc[j][1], acc[j][2], acc[j][3]);
            *(float4*)(op + (m0 + j) * 128 + n0 + 4) =
                make_float4(acc[j][4], acc[j][5], acc[j][6], acc[j][7]);
        }
    } else {
#pragma unroll
        for (int j = 0; j < 8; ++j) {
            float4 t0 = *(float4*)(op + (m0 + j) * 128 + n0);
            float4 t1 = *(float4*)(op + (m0 + j) * 128 + n0 + 4);
            t0.x += acc[j][0]; t0.y += acc[j][1]; t0.z += acc[j][2]; t0.w += acc[j][3];
            t1.x += acc[j][4]; t1.y += acc[j][5]; t1.z += acc[j][6]; t1.w += acc[j][7];
            *(float4*)(op + (m0 + j) * 128 + n0) = t0;
            *(float4*)(op + (m0 + j) * 128 + n0 + 4) = t1;
        }
    }
}

// ---------------------------------------------------------------------------
extern "C" void kernel_launch(void* const* d_in, const int* in_sizes, int n_in,
                              void* d_out, int out_size) {
    const float* x  = (const float*)d_in[0];
    const float* w0 = (const float*)d_in[1];
    const float* w1 = (const float*)d_in[2];
    float* out = (float*)d_out;

    (void)in_sizes; (void)n_in; (void)out_size;

    // >48KB dynamic smem opt-in (host-side calls, not captured as graph nodes)
    cudaFuncSetAttribute(k_mix, cudaFuncAttributeMaxDynamicSharedMemorySize, 4 * 64 * 68 * 4);
    cudaFuncSetAttribute(k_inv, cudaFuncAttributeMaxDynamicSharedMemorySize, 2 * 64 * 132 * 4);

    k_init<<<2112, 256>>>(w0, w1);

    // ---- branch Y (width / last axis), writes out ----
    k_fwd_y<<<2048, 256, 8448 * 4>>>(x);
    k_mix<<<2048, 256, 4 * 64 * 68 * 4>>>(0);
    k_inv<<<2048, 256, 2 * 64 * 132 * 4>>>(out, 0);

    // ---- branch X (height / axis -2), accumulates into out ----
    k_fwd_x<<<2048, 256, 8448 * 4>>>(x);
    k_mix<<<2048, 256, 4 * 64 * 68 * 4>>>(1);
    k_inv<<<2048, 256, 2 * 64 * 132 * 4>>>(out, 1);
}